// round 9
// baseline (speedup 1.0000x reference)
#include <cuda_runtime.h>
#include <cuda_bf16.h>
#include <math.h>
#define PI_F 3.14159265358979323846f
#define NS_MAX 524288
#define NR_MAX 16384
typedef unsigned int u32;

#define RA 33792
#define OFF_A 0
#define OFF_B 101376
#define OFF_FS 202752
#define OFF_PD 206848
#define OFF_MK0 208896
#define OFF_MK1 210944
#define SMEM_BYTES 212992

__device__ __forceinline__ u32 sm32(const void* p){u32 a;asm("{.reg .u64 t;cvta.to.shared.u64 t,%1;cvt.u32.u64 %0,t;}":"=r"(a):"l"(p));return a;}
__device__ __forceinline__ void LD4(u32* r,u32 a){asm volatile("ldmatrix.sync.aligned.m8n8.x4.shared.b16 {%0,%1,%2,%3},[%4];":"=r"(r[0]),"=r"(r[1]),"=r"(r[2]),"=r"(r[3]):"r"(a));}
__device__ __forceinline__ void MMA(float* d,const u32* a,u32 b0,u32 b1){
  asm volatile("mma.sync.aligned.m16n8k16.row.col.f32.bf16.bf16.f32 {%0,%1,%2,%3},{%4,%5,%6,%7},{%8,%9},{%0,%1,%2,%3};"
  :"+f"(d[0]),"+f"(d[1]),"+f"(d[2]),"+f"(d[3]):"r"(a[0]),"r"(a[1]),"r"(a[2]),"r"(a[3]),"r"(b0),"r"(b1));}
__device__ __forceinline__ u32 pk(float a,float b){
  return (u32)__bfloat16_as_ushort(__float2bfloat16(a))|((u32)__bfloat16_as_ushort(__float2bfloat16(b))<<16);}
__device__ __forceinline__ void split3(float a,float b,u32&h,u32&m,u32&l){
  float ah=__bfloat162float(__float2bfloat16(a)),bh=__bfloat162float(__float2bfloat16(b));
  float ra=a-ah,rb=b-bh;
  float am=__bfloat162float(__float2bfloat16(ra)),bm=__bfloat162float(__float2bfloat16(rb));
  h=pk(ah,bh);m=pk(ra,rb);l=pk(ra-am,rb-bm);}

__device__ __align__(16) __nv_bfloat16 W0[36864],W1[196608],WF[32768],WP[196608],WB[49152],Q0[16384],Q1[32768];
__device__ float g_a[NS_MAX],g_lg[NS_MAX],g_rgb[NS_MAX*3],g_nrm[NS_MAX*3];
__device__ int g_st[NR_MAX+1];

__device__ __forceinline__ void wsp3(__nv_bfloat16* A,int st,int i,float v){
  float l0=__bfloat162float(__float2bfloat16(v));float r=v-l0;
  float l1=__bfloat162float(__float2bfloat16(r));
  A[i]=__float2bfloat16(v);A[st+i]=__float2bfloat16(r);A[2*st+i]=__float2bfloat16(r-l1);}
__device__ __forceinline__ void wsp2(__nv_bfloat16* A,int st,int i,float v){
  float l0=__bfloat162float(__float2bfloat16(v));
  A[i]=__float2bfloat16(v);A[st+i]=__float2bfloat16(v-l0);}

__global__ void prep(const float* Wg0,const float* Wg1,const float* Wg2,const float* Wc0,const float* Wc1){
  int i=blockIdx.x*256+threadIdx.x;int n=i>>8,k=i&255;
  wsp3(W1,65536,i,Wg1[k*256+n]);
  wsp3(WP,65536,i,Wg1[n*256+k]*Wg2[k*16]);
  if(i<12288){int nn=i/48,kk=i%48;wsp3(W0,12288,i,(kk<39)?Wg0[kk*256+nn]:0.f);}
  if(i<16384){wsp2(WF,16384,i,(n<16)?Wg2[k*16+n]:0.f);
    wsp3(WB,16384,i,(n<39)?Wg0[n*256+k]:0.f);
    wsp2(Q1,16384,i,(n<3)?Wc1[k*3+n]:0.f);}
  if(i<8192){int nn=i/32,kk=i%32;wsp2(Q0,8192,i,(kk<25)?Wc0[kk*256+nn]:0.f);}
}

#define PRODJ(Af,Bf) {_Pragma("unroll") for(int j=0;j<4;j++) MMA(acc[ch][j],Af,Bf[(j>>1)*4+(j&1)],Bf[(j>>1)*4+(j&1)+2]);}

// SCH 0:P3(2-limb) 1:P6(3-limb) 2:P3m(exact A0, 3-limb B)
// EPI 0:relu+bias+mask->3limb A  1:relu+bias->2limb A  2:apply mask->3limb A  3:dump fp32 D
template<int NCH,int KS,int SCH,int EPI>
__device__ void gemm(char* smc,const __nv_bfloat16* G,int lstr,const float* bias,u32* MK,const u32* MKA){
  u32 sb=sm32(smc);const int tid=threadIdx.x,w=tid>>5,l=tid&31;
  const int mr0=(w&3)*16,lw=w>>2,nc0=lw*32,KB=KS*32;
  const int NBL=(SCH==0)?2:3;
  u32 ao=(mr0+(l&7)+((l&8)?8:0))*528+((l&16)?16:0);
  u32 bo=(nc0+(l&7)+((l&8)?8:0))*528+((l&16)?16:0);
  float acc[NCH][4][4];
#pragma unroll
  for(int c=0;c<NCH;c++)
#pragma unroll
    for(int j=0;j<4;j++)
#pragma unroll
      for(int q=0;q<4;q++)acc[c][j][q]=0.f;
  for(int ch=0;ch<NCH;ch++){
    __syncthreads();
#pragma unroll
    for(int b=0;b<NBL;b++){
      const char* src=(const char*)(G+(size_t)b*lstr)+(size_t)ch*64*KB;
      for(int i=tid*16;i<64*KB;i+=4096){int r=i/KB,k=i-r*KB;
        *(uint4*)(smc+OFF_B+b*RA+r*528+k)=*(const uint4*)(src+i);}}
    __syncthreads();
#pragma unroll 2
    for(int ks=0;ks<KS;ks++){
      u32 B0[8],B1[8],B2[8],A0[4],A1[4],A2[4];
      LD4(B0,sb+OFF_B+bo+ks*32);LD4(B0+4,sb+OFF_B+bo+16*528+ks*32);
      LD4(B1,sb+OFF_B+RA+bo+ks*32);LD4(B1+4,sb+OFF_B+RA+bo+16*528+ks*32);
      if(NBL==3){LD4(B2,sb+OFF_B+2*RA+bo+ks*32);LD4(B2+4,sb+OFF_B+2*RA+bo+16*528+ks*32);}
      LD4(A0,sb+OFF_A+ao+ks*32);
      if(SCH!=2)LD4(A1,sb+OFF_A+RA+ao+ks*32);
      if(SCH==1)LD4(A2,sb+OFF_A+2*RA+ao+ks*32);
      PRODJ(A0,B0)
      if(SCH==1){PRODJ(A1,B0) PRODJ(A0,B1) PRODJ(A2,B0) PRODJ(A1,B1) PRODJ(A0,B2)}
      if(SCH==0){PRODJ(A1,B0) PRODJ(A0,B1)}
      if(SCH==2){PRODJ(A0,B1) PRODJ(A0,B2)}
    }
  }
  __syncthreads();
  if(EPI==3){
    float* D=(float*)(smc+OFF_B);int m=mr0+(l>>2);
#pragma unroll
    for(int j=0;j<4;j++){int nn=nc0+8*j+2*(l&3);
      D[m*66+nn]=acc[0][j][0];D[m*66+nn+1]=acc[0][j][1];
      D[(m+8)*66+nn]=acc[0][j][2];D[(m+8)*66+nn+1]=acc[0][j][3];}
  }else{
#pragma unroll
    for(int ch=0;ch<NCH;ch++){
      int m=mr0+(l>>2),wd=ch*2+lw;u32 p0=0,p1=0;
#pragma unroll
      for(int j=0;j<4;j++){
        int nn=ch*64+nc0+8*j+2*(l&3),ps=8*j+2*(l&3);
        float v0=acc[ch][j][0],v1=acc[ch][j][1],v2=acc[ch][j][2],v3=acc[ch][j][3];
        if(EPI<=1){float b0=bias[nn],b1=bias[nn+1];
          v0=fmaxf(v0+b0,0.f);v1=fmaxf(v1+b1,0.f);v2=fmaxf(v2+b0,0.f);v3=fmaxf(v3+b1,0.f);}
        if(EPI==0){if(v0>0.f)p0|=1u<<ps;if(v1>0.f)p0|=1u<<(ps+1);if(v2>0.f)p1|=1u<<ps;if(v3>0.f)p1|=1u<<(ps+1);}
        if(EPI==2){u32 k0=MKA[m*8+wd],k1=MKA[(m+8)*8+wd];
          if(!((k0>>ps)&1))v0=0.f;if(!((k0>>(ps+1))&1))v1=0.f;
          if(!((k1>>ps)&1))v2=0.f;if(!((k1>>(ps+1))&1))v3=0.f;}
        u32 h,mm,lo;
        split3(v0,v1,h,mm,lo);
        *(u32*)(smc+OFF_A+m*528+nn*2)=h;*(u32*)(smc+OFF_A+RA+m*528+nn*2)=mm;
        if(EPI!=1)*(u32*)(smc+OFF_A+2*RA+m*528+nn*2)=lo;
        split3(v2,v3,h,mm,lo);
        *(u32*)(smc+OFF_A+(m+8)*528+nn*2)=h;*(u32*)(smc+OFF_A+RA+(m+8)*528+nn*2)=mm;
        if(EPI!=1)*(u32*)(smc+OFF_A+2*RA+(m+8)*528+nn*2)=lo;}
      if(EPI==0){
        p0|=__shfl_xor_sync(~0u,p0,1);p0|=__shfl_xor_sync(~0u,p0,2);
        p1|=__shfl_xor_sync(~0u,p1,1);p1|=__shfl_xor_sync(~0u,p1,2);
        if((l&3)==0){MK[m*8+wd]=p0;MK[(m+8)*8+wd]=p1;}}}
  }
  __syncthreads();
}

template<bool RAND>
__global__ void __launch_bounds__(256,1) fused(
  const float* __restrict__ rays_o,const float* __restrict__ rays_d,
  const int* __restrict__ ridx,const float* __restrict__ t_starts,
  const float* __restrict__ pts,const float* __restrict__ s_var,
  const float* __restrict__ bg0,const float* __restrict__ bg1,
  const float* __restrict__ bg2,const float* __restrict__ bc0,
  const float* __restrict__ bc1,
  float* __restrict__ out,int nn,long long off_sdf){
  extern __shared__ char smc[];
  float* PD=(float*)(smc+OFF_PD);float* FS=(float*)(smc+OFF_FS);
  u32* MK0=(u32*)(smc+OFF_MK0);u32* MK1=(u32*)(smc+OFF_MK1);
  const int tid=threadIdx.x;const int gs=blockIdx.x*64+tid;
  if(tid<64){
    int si=(gs<nn)?gs:nn-1;float px,py,pz;
    if(RAND){px=pts[si*3];py=pts[si*3+1];pz=pts[si*3+2];}
    else{
      int ray=ridx[si];
      float ox=rays_o[ray*3],oy=rays_o[ray*3+1],oz=rays_o[ray*3+2];
      float dx=rays_d[ray*3],dy=rays_d[ray*3+1],dz=rays_d[ray*3+2];
      float inv=1.f/(sqrtf(dx*dx+dy*dy+dz*dz)+1e-10f);
      dx*=inv;dy*=inv;dz*=inv;
      float mid=t_starts[si]+0.0025f;
      px=fmaf(dx,mid,ox);py=fmaf(dy,mid,oy);pz=fmaf(dz,mid,oz);
      PD[tid*8]=px;PD[tid*8+1]=py;PD[tid*8+2]=pz;
      PD[tid*8+3]=dx;PD[tid*8+4]=dy;PD[tid*8+5]=dz;}
    float pe[48];
#pragma unroll
    for(int j=39;j<48;j++)pe[j]=0.f;
    pe[0]=px;pe[1]=py;pe[2]=pz;
    float f=PI_F;
#pragma unroll
    for(int i=0;i<6;i++){
      float sx,cx,sy,cy,sz,cz;
      sincosf(f*px,&sx,&cx);sincosf(f*py,&sy,&cy);sincosf(f*pz,&sz,&cz);
      pe[3+6*i]=sx;pe[4+6*i]=sy;pe[5+6*i]=sz;pe[6+6*i]=cx;pe[7+6*i]=cy;pe[8+6*i]=cz;f*=2.f;}
#pragma unroll
    for(int j=0;j<24;j++){u32 h,m,lo;split3(pe[2*j],pe[2*j+1],h,m,lo);
      *(u32*)(smc+OFF_A+tid*528+j*4)=h;*(u32*)(smc+OFF_A+RA+tid*528+j*4)=m;*(u32*)(smc+OFF_A+2*RA+tid*528+j*4)=lo;}
  }
  gemm<4,3,1,0>(smc,W0,12288,bg0,MK0,0);
  gemm<4,16,1,0>(smc,W1,65536,bg1,MK1,0);
  gemm<1,16,0,3>(smc,WF,16384,0,0,0);
  {float* D=(float*)(smc+OFF_B);
   if(tid<64){
     float sdf=D[tid*66]+bg2[0];FS[tid*16]=sdf;
     if(gs<nn)out[off_sdf+gs]=sdf;
     for(int c=1;c<16;c++)FS[tid*16+c]=D[tid*66+c]+bg2[c];}}
  if(RAND)return;
  if(tid<64){
    for(int j=0;j<128;j++){u32 mk=MK1[tid*8+(j>>4)];int ps=(j&15)*2;
      *(u32*)(smc+OFF_A+tid*528+j*4)=(((mk>>ps)&1)?0x3F80u:0u)|(((mk>>(ps+1))&1)?0x3F800000u:0u);}}
  gemm<4,16,2,2>(smc,WP,65536,0,0,MK0);
  gemm<1,16,1,3>(smc,WB,16384,0,0,0);
  if(tid<64){
    float* D=(float*)(smc+OFF_B);
    float px=PD[tid*8],py=PD[tid*8+1],pz=PD[tid*8+2];
    float dx=PD[tid*8+3],dy=PD[tid*8+4],dz=PD[tid*8+5];
    float g0=D[tid*66],g1=D[tid*66+1],g2=D[tid*66+2];
    float f=PI_F;
#pragma unroll
    for(int i=0;i<6;i++){
      float sx,cx,sy,cy,sz,cz;
      sincosf(f*px,&sx,&cx);sincosf(f*py,&sy,&cy);sincosf(f*pz,&sz,&cz);
      g0+=f*(cx*D[tid*66+3+6*i]-sx*D[tid*66+6+6*i]);
      g1+=f*(cy*D[tid*66+4+6*i]-sy*D[tid*66+7+6*i]);
      g2+=f*(cz*D[tid*66+5+6*i]-sz*D[tid*66+8+6*i]);f*=2.f;}
    float len=sqrtf(g0*g0+g1*g1+g2*g2),ninv=1.f/(len+1e-10f);
    float nx=g0*ninv,ny=g1*ninv,nz=g2*ninv;
    float inv_s=fminf(fmaxf(expf(s_var[0]),1e-6f),1e6f);
    float dsdf=fminf(g0*dx+g1*dy+g2*dz,0.f);
    float sdf=FS[tid*16];
    float cdf=1.f/(1.f+expf(-inv_s*sdf));
    float rho=fmaxf(inv_s*(cdf-1.f)*dsdf,0.f);
    float a=fminf(fmaxf(1.f-expf(-rho*0.005f),0.f),1.f-1e-7f);
    if(gs<nn){g_a[gs]=a;g_lg[gs]=log1pf(-a);
      g_nrm[gs*3]=nx;g_nrm[gs*3+1]=ny;g_nrm[gs*3+2]=nz;}
    float ci[32];
#pragma unroll
    for(int j=25;j<32;j++)ci[j]=0.f;
    ci[0]=dx;ci[1]=dy;ci[2]=dz;
#pragma unroll
    for(int c=0;c<16;c++)ci[3+c]=FS[tid*16+c];
    ci[19]=px;ci[20]=py;ci[21]=pz;ci[22]=nx;ci[23]=ny;ci[24]=nz;
#pragma unroll
    for(int j=0;j<16;j++){u32 h,m,lo;split3(ci[2*j],ci[2*j+1],h,m,lo);
      *(u32*)(smc+OFF_A+tid*528+j*4)=h;*(u32*)(smc+OFF_A+RA+tid*528+j*4)=m;}
  }
  gemm<4,2,0,1>(smc,Q0,8192,bc0,0,0);
  gemm<1,16,0,3>(smc,Q1,16384,0,0,0);
  if(tid<64&&gs<nn){
    float* D=(float*)(smc+OFF_B);
    for(int c=0;c<3;c++)g_rgb[gs*3+c]=1.f/(1.f+expf(-(D[tid*66+c]+bc1[c])));}
}

__global__ void ray_starts(const int* __restrict__ ridx,int n_rays,int n_samples){
  int r=blockIdx.x*256+threadIdx.x;
  if(r>n_rays)return;
  int lo=0,hi=n_samples;
  while(lo<hi){int m=(lo+hi)>>1;if(ridx[m]<r)lo=m+1;else hi=m;}
  g_st[r]=lo;
}

__global__ void composite(const float* __restrict__ t_starts,float* __restrict__ out,
                          int n_rays,long long off_c,long long off_n,
                          long long off_o,long long off_d,long long off_w){
  int ray=(blockIdx.x*blockDim.x+threadIdx.x)>>5;
  int lane=threadIdx.x&31;
  if(ray>=n_rays)return;
  int s0=g_st[ray],s1=g_st[ray+1];
  float carry=0.f,op=0.f,dep=0.f,c0=0.f,c1=0.f,c2=0.f,n0=0.f,n1=0.f,n2=0.f;
  for(int base=s0;base<s1;base+=32){
    int s=base+lane;bool v=s<s1;
    float lg=v?g_lg[s]:0.f,incl=lg;
#pragma unroll
    for(int o=1;o<32;o<<=1){float t=__shfl_up_sync(~0u,incl,o);if(lane>=o)incl+=t;}
    if(v){
      float wgt=g_a[s]*expf(carry+incl-lg);
      out[off_w+s]=wgt;
      float mid=t_starts[s]+0.0025f;
      op+=wgt;dep+=wgt*mid;
      c0+=wgt*g_rgb[s*3];c1+=wgt*g_rgb[s*3+1];c2+=wgt*g_rgb[s*3+2];
      n0+=wgt*g_nrm[s*3];n1+=wgt*g_nrm[s*3+1];n2+=wgt*g_nrm[s*3+2];}
    carry+=__shfl_sync(~0u,incl,31);
  }
#pragma unroll
  for(int o=16;o;o>>=1){
    op+=__shfl_xor_sync(~0u,op,o);dep+=__shfl_xor_sync(~0u,dep,o);
    c0+=__shfl_xor_sync(~0u,c0,o);c1+=__shfl_xor_sync(~0u,c1,o);
    c2+=__shfl_xor_sync(~0u,c2,o);n0+=__shfl_xor_sync(~0u,n0,o);
    n1+=__shfl_xor_sync(~0u,n1,o);n2+=__shfl_xor_sync(~0u,n2,o);}
  if(lane==0){
    out[off_o+ray]=op;out[off_d+ray]=dep;
    out[off_c+ray*3]=c0;out[off_c+ray*3+1]=c1;out[off_c+ray*3+2]=c2;
    float nl=sqrtf(n0*n0+n1*n1+n2*n2),ninv=1.f/(nl+1e-10f);
    out[off_n+ray*3]=n0*ninv;out[off_n+ray*3+1]=n1*ninv;out[off_n+ray*3+2]=n2*ninv;}
}

extern "C" void kernel_launch(void* const* d_in,const int* in_sizes,int n_in,
                              void* d_out,int out_size){
  const float* rays_o=(const float*)d_in[0];
  const float* rays_d=(const float*)d_in[1];
  const int*   ridx  =(const int*)d_in[2];
  const float* t_st  =(const float*)d_in[3];
  const float* rpts  =(const float*)d_in[4];
  const float* s_var =(const float*)d_in[5];
  const float* Wg0=(const float*)d_in[6];  const float* bg0=(const float*)d_in[7];
  const float* Wg1=(const float*)d_in[8];  const float* bg1=(const float*)d_in[9];
  const float* Wg2=(const float*)d_in[10]; const float* bg2=(const float*)d_in[11];
  const float* Wc0=(const float*)d_in[12]; const float* bc0=(const float*)d_in[13];
  const float* Wc1=(const float*)d_in[14]; const float* bc1=(const float*)d_in[15];
  float* out=(float*)d_out;
  int n_rays=in_sizes[0]/3,n_samples=in_sizes[2],n_rand=in_sizes[4]/3;
  long long off_c=0;
  long long off_n=off_c+3LL*n_rays;
  long long off_o=off_n+3LL*n_rays;
  long long off_d=off_o+n_rays;
  long long off_w=off_d+n_rays;
  long long off_s=off_w+n_samples;
  long long off_r=off_s+n_samples;
  cudaFuncSetAttribute(fused<false>,cudaFuncAttributeMaxDynamicSharedMemorySize,SMEM_BYTES);
  cudaFuncSetAttribute(fused<true>, cudaFuncAttributeMaxDynamicSharedMemorySize,SMEM_BYTES);
  prep<<<256,256>>>(Wg0,Wg1,Wg2,Wc0,Wc1);
  fused<false><<<(n_samples+63)/64,256,SMEM_BYTES>>>(
    rays_o,rays_d,ridx,t_st,rpts,s_var,bg0,bg1,bg2,bc0,bc1,out,n_samples,off_s);
  fused<true><<<(n_rand+63)/64,256,SMEM_BYTES>>>(
    rays_o,rays_d,ridx,t_st,rpts,s_var,bg0,bg1,bg2,bc0,bc1,out,n_rand,off_r);
  ray_starts<<<(n_rays+256)/256,256>>>(ridx,n_rays,n_samples);
  composite<<<(n_rays*32+255)/256,256>>>(t_st,out,n_rays,off_c,off_n,off_o,off_d,off_w);
}

// round 10
// speedup vs baseline: 1.3976x; 1.3976x over previous
#include <cuda_runtime.h>
#include <cuda_bf16.h>
#include <math.h>
#define PI_F 3.14159265358979323846f
#define NS_MAX 524288
#define NR_MAX 16384
typedef unsigned int u32;

#define RA 33792
#define OFF_A 0
#define OFF_B 101376
#define OFF_FS 202752
#define OFF_PD 206848
#define OFF_MK0 208896
#define OFF_MK1 212992
#define SMEM_BYTES 217088

__device__ __forceinline__ u32 sm32(const void* p){u32 a;asm("{.reg .u64 t;cvta.to.shared.u64 t,%1;cvt.u32.u64 %0,t;}":"=r"(a):"l"(p));return a;}
__device__ __forceinline__ void LD4(u32* r,u32 a){asm volatile("ldmatrix.sync.aligned.m8n8.x4.shared.b16 {%0,%1,%2,%3},[%4];":"=r"(r[0]),"=r"(r[1]),"=r"(r[2]),"=r"(r[3]):"r"(a));}
__device__ __forceinline__ void MMA(float* d,const u32* a,u32 b0,u32 b1){
  asm volatile("mma.sync.aligned.m16n8k16.row.col.f32.bf16.bf16.f32 {%0,%1,%2,%3},{%4,%5,%6,%7},{%8,%9},{%0,%1,%2,%3};"
  :"+f"(d[0]),"+f"(d[1]),"+f"(d[2]),"+f"(d[3]):"r"(a[0]),"r"(a[1]),"r"(a[2]),"r"(a[3]),"r"(b0),"r"(b1));}
__device__ __forceinline__ void CPA(u32 dst,const void* src){
  asm volatile("cp.async.cg.shared.global [%0],[%1],16;"::"r"(dst),"l"(src));}
__device__ __forceinline__ void CPWAIT(){
  asm volatile("cp.async.commit_group;\ncp.async.wait_group 0;":::"memory");}
__device__ __forceinline__ u32 pk(float a,float b){
  return (u32)__bfloat16_as_ushort(__float2bfloat16(a))|((u32)__bfloat16_as_ushort(__float2bfloat16(b))<<16);}
__device__ __forceinline__ void split3(float a,float b,u32&h,u32&m,u32&l){
  float ah=__bfloat162float(__float2bfloat16(a)),bh=__bfloat162float(__float2bfloat16(b));
  float ra=a-ah,rb=b-bh;
  float am=__bfloat162float(__float2bfloat16(ra)),bm=__bfloat162float(__float2bfloat16(rb));
  h=pk(ah,bh);m=pk(ra,rb);l=pk(ra-am,rb-bm);}

__device__ __align__(16) __nv_bfloat16 W0[36864],W1[196608],WF[32768],WP[196608],WB[49152],Q0[16384],Q1[32768];
__device__ float g_a[NS_MAX],g_lg[NS_MAX],g_rgb[NS_MAX*3],g_nrm[NS_MAX*3];
__device__ int g_st[NR_MAX+1];

__device__ __forceinline__ void wsp3(__nv_bfloat16* A,int st,int i,float v){
  float l0=__bfloat162float(__float2bfloat16(v));float r=v-l0;
  float l1=__bfloat162float(__float2bfloat16(r));
  A[i]=__float2bfloat16(v);A[st+i]=__float2bfloat16(r);A[2*st+i]=__float2bfloat16(r-l1);}
__device__ __forceinline__ void wsp2(__nv_bfloat16* A,int st,int i,float v){
  float l0=__bfloat162float(__float2bfloat16(v));
  A[i]=__float2bfloat16(v);A[st+i]=__float2bfloat16(v-l0);}

__global__ void prep(const float* Wg0,const float* Wg1,const float* Wg2,const float* Wc0,const float* Wc1){
  int i=blockIdx.x*256+threadIdx.x;int n=i>>8,k=i&255;
  wsp3(W1,65536,i,Wg1[k*256+n]);
  wsp3(WP,65536,i,Wg1[n*256+k]*Wg2[k*16]);
  if(i<12288){int nn=i/48,kk=i%48;wsp3(W0,12288,i,(kk<39)?Wg0[kk*256+nn]:0.f);}
  if(i<16384){wsp2(WF,16384,i,(n<16)?Wg2[k*16+n]:0.f);
    wsp3(WB,16384,i,(n<39)?Wg0[n*256+k]:0.f);
    wsp2(Q1,16384,i,(n<3)?Wc1[k*3+n]:0.f);}
  if(i<8192){int nn=i/32,kk=i%32;wsp2(Q0,8192,i,(kk<25)?Wc0[kk*256+nn]:0.f);}
}

#define PRODJ(Af,Bf) {MMA(acc[ch][0],Af,Bf[0],Bf[2]);MMA(acc[ch][1],Af,Bf[1],Bf[3]);}

// SCH 0:P3(2-limb) 1:P6(3-limb) 2:P3m(exact A0, 3-limb B)
// EPI 0:relu+bias+mask->3limb A  1:relu+bias->2limb A  2:apply mask->3limb A  3:dump fp32 D
template<int NCH,int KS,int SCH,int EPI>
__device__ void gemm(char* smc,const __nv_bfloat16* G,int lstr,const float* bias,u32* MK,const u32* MKA){
  u32 sb=sm32(smc);const int tid=threadIdx.x,w=tid>>5,l=tid&31;
  const int mr0=(w&3)*16,lw=w>>2,nc0=lw*16,KB=KS*32;
  const int NBL=(SCH==0)?2:3;
  u32 ao=(mr0+(l&7)+((l&8)?8:0))*528+((l&16)?16:0);
  u32 bo=(nc0+(l&7)+((l&8)?8:0))*528+((l&16)?16:0);
  float acc[NCH][2][4];
#pragma unroll
  for(int c=0;c<NCH;c++)
#pragma unroll
    for(int j=0;j<2;j++)
#pragma unroll
      for(int q=0;q<4;q++)acc[c][j][q]=0.f;
  for(int ch=0;ch<NCH;ch++){
    __syncthreads();
    for(int i=tid*16;i<64*KB;i+=8192){int r=i/KB,k=i-r*KB;
#pragma unroll
      for(int b=0;b<NBL;b++)
        CPA(sb+OFF_B+b*RA+r*528+k,(const char*)(G+(size_t)b*lstr)+(size_t)ch*64*KB+i);}
    CPWAIT();
    __syncthreads();
#pragma unroll 2
    for(int ks=0;ks<KS;ks++){
      u32 B0[4],B1[4],B2[4],A0[4],A1[4],A2[4];
      LD4(B0,sb+OFF_B+bo+ks*32);
      LD4(B1,sb+OFF_B+RA+bo+ks*32);
      if(NBL==3)LD4(B2,sb+OFF_B+2*RA+bo+ks*32);
      LD4(A0,sb+OFF_A+ao+ks*32);
      if(SCH!=2)LD4(A1,sb+OFF_A+RA+ao+ks*32);
      if(SCH==1)LD4(A2,sb+OFF_A+2*RA+ao+ks*32);
      PRODJ(A0,B0)
      if(SCH==1){PRODJ(A1,B0) PRODJ(A0,B1) PRODJ(A2,B0) PRODJ(A1,B1) PRODJ(A0,B2)}
      if(SCH==0){PRODJ(A1,B0) PRODJ(A0,B1)}
      if(SCH==2){PRODJ(A0,B1) PRODJ(A0,B2)}
    }
  }
  __syncthreads();
  if(EPI==3){
    float* D=(float*)(smc+OFF_B);int m=mr0+(l>>2);
#pragma unroll
    for(int j=0;j<2;j++){int nn=nc0+8*j+2*(l&3);
      D[m*66+nn]=acc[0][j][0];D[m*66+nn+1]=acc[0][j][1];
      D[(m+8)*66+nn]=acc[0][j][2];D[(m+8)*66+nn+1]=acc[0][j][3];}
  }else{
#pragma unroll
    for(int ch=0;ch<NCH;ch++){
      int m=mr0+(l>>2),wd=ch*4+lw;u32 p0=0,p1=0;
#pragma unroll
      for(int j=0;j<2;j++){
        int nn=ch*64+nc0+8*j+2*(l&3),ps=8*j+2*(l&3);
        float v0=acc[ch][j][0],v1=acc[ch][j][1],v2=acc[ch][j][2],v3=acc[ch][j][3];
        if(EPI<=1){float b0=bias[nn],b1=bias[nn+1];
          v0=fmaxf(v0+b0,0.f);v1=fmaxf(v1+b1,0.f);v2=fmaxf(v2+b0,0.f);v3=fmaxf(v3+b1,0.f);}
        if(EPI==0){if(v0>0.f)p0|=1u<<ps;if(v1>0.f)p0|=1u<<(ps+1);if(v2>0.f)p1|=1u<<ps;if(v3>0.f)p1|=1u<<(ps+1);}
        if(EPI==2){u32 k0=MKA[m*16+wd],k1=MKA[(m+8)*16+wd];
          if(!((k0>>ps)&1))v0=0.f;if(!((k0>>(ps+1))&1))v1=0.f;
          if(!((k1>>ps)&1))v2=0.f;if(!((k1>>(ps+1))&1))v3=0.f;}
        u32 h,mm,lo;
        split3(v0,v1,h,mm,lo);
        *(u32*)(smc+OFF_A+m*528+nn*2)=h;*(u32*)(smc+OFF_A+RA+m*528+nn*2)=mm;
        if(EPI!=1)*(u32*)(smc+OFF_A+2*RA+m*528+nn*2)=lo;
        split3(v2,v3,h,mm,lo);
        *(u32*)(smc+OFF_A+(m+8)*528+nn*2)=h;*(u32*)(smc+OFF_A+RA+(m+8)*528+nn*2)=mm;
        if(EPI!=1)*(u32*)(smc+OFF_A+2*RA+(m+8)*528+nn*2)=lo;}
      if(EPI==0){
        p0|=__shfl_xor_sync(~0u,p0,1);p0|=__shfl_xor_sync(~0u,p0,2);
        p1|=__shfl_xor_sync(~0u,p1,1);p1|=__shfl_xor_sync(~0u,p1,2);
        if((l&3)==0){MK[m*16+wd]=p0;MK[(m+8)*16+wd]=p1;}}}
  }
  __syncthreads();
}

template<bool RAND>
__global__ void __launch_bounds__(512,1) fused(
  const float* __restrict__ rays_o,const float* __restrict__ rays_d,
  const int* __restrict__ ridx,const float* __restrict__ t_starts,
  const float* __restrict__ pts,const float* __restrict__ s_var,
  const float* __restrict__ bg0,const float* __restrict__ bg1,
  const float* __restrict__ bg2,const float* __restrict__ bc0,
  const float* __restrict__ bc1,
  float* __restrict__ out,int nn,long long off_sdf){
  extern __shared__ char smc[];
  float* PD=(float*)(smc+OFF_PD);float* FS=(float*)(smc+OFF_FS);
  u32* MK0=(u32*)(smc+OFF_MK0);u32* MK1=(u32*)(smc+OFF_MK1);
  const int tid=threadIdx.x;const int gs=blockIdx.x*64+tid;
  if(tid<64){
    int si=(gs<nn)?gs:nn-1;float px,py,pz;
    if(RAND){px=pts[si*3];py=pts[si*3+1];pz=pts[si*3+2];}
    else{
      int ray=ridx[si];
      float ox=rays_o[ray*3],oy=rays_o[ray*3+1],oz=rays_o[ray*3+2];
      float dx=rays_d[ray*3],dy=rays_d[ray*3+1],dz=rays_d[ray*3+2];
      float inv=1.f/(sqrtf(dx*dx+dy*dy+dz*dz)+1e-10f);
      dx*=inv;dy*=inv;dz*=inv;
      float mid=t_starts[si]+0.0025f;
      px=fmaf(dx,mid,ox);py=fmaf(dy,mid,oy);pz=fmaf(dz,mid,oz);
      PD[tid*8]=px;PD[tid*8+1]=py;PD[tid*8+2]=pz;
      PD[tid*8+3]=dx;PD[tid*8+4]=dy;PD[tid*8+5]=dz;}
    float pe[48];
#pragma unroll
    for(int j=39;j<48;j++)pe[j]=0.f;
    pe[0]=px;pe[1]=py;pe[2]=pz;
    float f=PI_F;
#pragma unroll
    for(int i=0;i<6;i++){
      float sx,cx,sy,cy,sz,cz;
      sincosf(f*px,&sx,&cx);sincosf(f*py,&sy,&cy);sincosf(f*pz,&sz,&cz);
      pe[3+6*i]=sx;pe[4+6*i]=sy;pe[5+6*i]=sz;pe[6+6*i]=cx;pe[7+6*i]=cy;pe[8+6*i]=cz;f*=2.f;}
#pragma unroll
    for(int j=0;j<24;j++){u32 h,m,lo;split3(pe[2*j],pe[2*j+1],h,m,lo);
      *(u32*)(smc+OFF_A+tid*528+j*4)=h;*(u32*)(smc+OFF_A+RA+tid*528+j*4)=m;*(u32*)(smc+OFF_A+2*RA+tid*528+j*4)=lo;}
  }
  gemm<4,3,1,0>(smc,W0,12288,bg0,MK0,0);
  gemm<4,16,1,0>(smc,W1,65536,bg1,MK1,0);
  gemm<1,16,0,3>(smc,WF,16384,0,0,0);
  {float* D=(float*)(smc+OFF_B);
   if(tid<64){
     float sdf=D[tid*66]+bg2[0];FS[tid*16]=sdf;
     if(gs<nn)out[off_sdf+gs]=sdf;
     for(int c=1;c<16;c++)FS[tid*16+c]=D[tid*66+c]+bg2[c];}}
  if(RAND)return;
  for(int idx=tid;idx<64*128;idx+=512){int r=idx>>7,j=idx&127;
    u32 mk=MK1[r*16+(j>>3)];int ps=(j&7)*2;
    *(u32*)(smc+OFF_A+r*528+j*4)=(((mk>>ps)&1)?0x3F80u:0u)|(((mk>>(ps+1))&1)?0x3F800000u:0u);}
  gemm<4,16,2,2>(smc,WP,65536,0,0,MK0);
  gemm<1,16,1,3>(smc,WB,16384,0,0,0);
  if(tid<64){
    float* D=(float*)(smc+OFF_B);
    float px=PD[tid*8],py=PD[tid*8+1],pz=PD[tid*8+2];
    float dx=PD[tid*8+3],dy=PD[tid*8+4],dz=PD[tid*8+5];
    float g0=D[tid*66],g1=D[tid*66+1],g2=D[tid*66+2];
    float f=PI_F;
#pragma unroll
    for(int i=0;i<6;i++){
      float sx,cx,sy,cy,sz,cz;
      sincosf(f*px,&sx,&cx);sincosf(f*py,&sy,&cy);sincosf(f*pz,&sz,&cz);
      g0+=f*(cx*D[tid*66+3+6*i]-sx*D[tid*66+6+6*i]);
      g1+=f*(cy*D[tid*66+4+6*i]-sy*D[tid*66+7+6*i]);
      g2+=f*(cz*D[tid*66+5+6*i]-sz*D[tid*66+8+6*i]);f*=2.f;}
    float len=sqrtf(g0*g0+g1*g1+g2*g2),ninv=1.f/(len+1e-10f);
    float nx=g0*ninv,ny=g1*ninv,nz=g2*ninv;
    float inv_s=fminf(fmaxf(expf(s_var[0]),1e-6f),1e6f);
    float dsdf=fminf(g0*dx+g1*dy+g2*dz,0.f);
    float sdf=FS[tid*16];
    float cdf=1.f/(1.f+expf(-inv_s*sdf));
    float rho=fmaxf(inv_s*(cdf-1.f)*dsdf,0.f);
    float a=fminf(fmaxf(1.f-expf(-rho*0.005f),0.f),1.f-1e-7f);
    if(gs<nn){g_a[gs]=a;g_lg[gs]=log1pf(-a);
      g_nrm[gs*3]=nx;g_nrm[gs*3+1]=ny;g_nrm[gs*3+2]=nz;}
    float ci[32];
#pragma unroll
    for(int j=25;j<32;j++)ci[j]=0.f;
    ci[0]=dx;ci[1]=dy;ci[2]=dz;
#pragma unroll
    for(int c=0;c<16;c++)ci[3+c]=FS[tid*16+c];
    ci[19]=px;ci[20]=py;ci[21]=pz;ci[22]=nx;ci[23]=ny;ci[24]=nz;
#pragma unroll
    for(int j=0;j<16;j++){u32 h,m,lo;split3(ci[2*j],ci[2*j+1],h,m,lo);
      *(u32*)(smc+OFF_A+tid*528+j*4)=h;*(u32*)(smc+OFF_A+RA+tid*528+j*4)=m;}
  }
  gemm<4,2,0,1>(smc,Q0,8192,bc0,0,0);
  gemm<1,16,0,3>(smc,Q1,16384,0,0,0);
  if(tid<64&&gs<nn){
    float* D=(float*)(smc+OFF_B);
    for(int c=0;c<3;c++)g_rgb[gs*3+c]=1.f/(1.f+expf(-(D[tid*66+c]+bc1[c])));}
}

__global__ void ray_starts(const int* __restrict__ ridx,int n_rays,int n_samples){
  int r=blockIdx.x*256+threadIdx.x;
  if(r>n_rays)return;
  int lo=0,hi=n_samples;
  while(lo<hi){int m=(lo+hi)>>1;if(ridx[m]<r)lo=m+1;else hi=m;}
  g_st[r]=lo;
}

__global__ void composite(const float* __restrict__ t_starts,float* __restrict__ out,
                          int n_rays,long long off_c,long long off_n,
                          long long off_o,long long off_d,long long off_w){
  int ray=(blockIdx.x*blockDim.x+threadIdx.x)>>5;
  int lane=threadIdx.x&31;
  if(ray>=n_rays)return;
  int s0=g_st[ray],s1=g_st[ray+1];
  float carry=0.f,op=0.f,dep=0.f,c0=0.f,c1=0.f,c2=0.f,n0=0.f,n1=0.f,n2=0.f;
  for(int base=s0;base<s1;base+=32){
    int s=base+lane;bool v=s<s1;
    float lg=v?g_lg[s]:0.f,incl=lg;
#pragma unroll
    for(int o=1;o<32;o<<=1){float t=__shfl_up_sync(~0u,incl,o);if(lane>=o)incl+=t;}
    if(v){
      float wgt=g_a[s]*expf(carry+incl-lg);
      out[off_w+s]=wgt;
      float mid=t_starts[s]+0.0025f;
      op+=wgt;dep+=wgt*mid;
      c0+=wgt*g_rgb[s*3];c1+=wgt*g_rgb[s*3+1];c2+=wgt*g_rgb[s*3+2];
      n0+=wgt*g_nrm[s*3];n1+=wgt*g_nrm[s*3+1];n2+=wgt*g_nrm[s*3+2];}
    carry+=__shfl_sync(~0u,incl,31);
  }
#pragma unroll
  for(int o=16;o;o>>=1){
    op+=__shfl_xor_sync(~0u,op,o);dep+=__shfl_xor_sync(~0u,dep,o);
    c0+=__shfl_xor_sync(~0u,c0,o);c1+=__shfl_xor_sync(~0u,c1,o);
    c2+=__shfl_xor_sync(~0u,c2,o);n0+=__shfl_xor_sync(~0u,n0,o);
    n1+=__shfl_xor_sync(~0u,n1,o);n2+=__shfl_xor_sync(~0u,n2,o);}
  if(lane==0){
    out[off_o+ray]=op;out[off_d+ray]=dep;
    out[off_c+ray*3]=c0;out[off_c+ray*3+1]=c1;out[off_c+ray*3+2]=c2;
    float nl=sqrtf(n0*n0+n1*n1+n2*n2),ninv=1.f/(nl+1e-10f);
    out[off_n+ray*3]=n0*ninv;out[off_n+ray*3+1]=n1*ninv;out[off_n+ray*3+2]=n2*ninv;}
}

extern "C" void kernel_launch(void* const* d_in,const int* in_sizes,int n_in,
                              void* d_out,int out_size){
  const float* rays_o=(const float*)d_in[0];
  const float* rays_d=(const float*)d_in[1];
  const int*   ridx  =(const int*)d_in[2];
  const float* t_st  =(const float*)d_in[3];
  const float* rpts  =(const float*)d_in[4];
  const float* s_var =(const float*)d_in[5];
  const float* Wg0=(const float*)d_in[6];  const float* bg0=(const float*)d_in[7];
  const float* Wg1=(const float*)d_in[8];  const float* bg1=(const float*)d_in[9];
  const float* Wg2=(const float*)d_in[10]; const float* bg2=(const float*)d_in[11];
  const float* Wc0=(const float*)d_in[12]; const float* bc0=(const float*)d_in[13];
  const float* Wc1=(const float*)d_in[14]; const float* bc1=(const float*)d_in[15];
  float* out=(float*)d_out;
  int n_rays=in_sizes[0]/3,n_samples=in_sizes[2],n_rand=in_sizes[4]/3;
  long long off_c=0;
  long long off_n=off_c+3LL*n_rays;
  long long off_o=off_n+3LL*n_rays;
  long long off_d=off_o+n_rays;
  long long off_w=off_d+n_rays;
  long long off_s=off_w+n_samples;
  long long off_r=off_s+n_samples;
  cudaFuncSetAttribute(fused<false>,cudaFuncAttributeMaxDynamicSharedMemorySize,SMEM_BYTES);
  cudaFuncSetAttribute(fused<true>, cudaFuncAttributeMaxDynamicSharedMemorySize,SMEM_BYTES);
  prep<<<256,256>>>(Wg0,Wg1,Wg2,Wc0,Wc1);
  fused<false><<<(n_samples+63)/64,512,SMEM_BYTES>>>(
    rays_o,rays_d,ridx,t_st,rpts,s_var,bg0,bg1,bg2,bc0,bc1,out,n_samples,off_s);
  fused<true><<<(n_rand+63)/64,512,SMEM_BYTES>>>(
    rays_o,rays_d,ridx,t_st,rpts,s_var,bg0,bg1,bg2,bc0,bc1,out,n_rand,off_r);
  ray_starts<<<(n_rays+256)/256,256>>>(ridx,n_rays,n_samples);
  composite<<<(n_rays*32+255)/256,256>>>(t_st,out,n_rays,off_c,off_n,off_o,off_d,off_w);
}

// round 11
// speedup vs baseline: 2.6432x; 1.8912x over previous
#include <cuda_runtime.h>
#include <cuda_fp16.h>
#include <math.h>
#define PI_F 3.14159265358979323846f
#define NS_MAX 524288
#define NR_MAX 16384
typedef unsigned int u32;

#define RB 33792
#define OFF_A 0
#define OFF_A1 67584
#define OFF_B 135168
#define OFF_FS 202752
#define OFF_PD 210944
#define OFF_MK0 215040
#define OFF_MK1 219136
#define SMEM_BYTES 223232

__device__ __forceinline__ u32 sm32(const void* p){u32 a;asm("{.reg .u64 t;cvta.to.shared.u64 t,%1;cvt.u32.u64 %0,t;}":"=r"(a):"l"(p));return a;}
__device__ __forceinline__ void LD4(u32* r,u32 a){asm volatile("ldmatrix.sync.aligned.m8n8.x4.shared.b16 {%0,%1,%2,%3},[%4];":"=r"(r[0]),"=r"(r[1]),"=r"(r[2]),"=r"(r[3]):"r"(a));}
__device__ __forceinline__ void MMA(float* d,const u32* a,u32 b0,u32 b1){
  asm volatile("mma.sync.aligned.m16n8k16.row.col.f32.f16.f16.f32 {%0,%1,%2,%3},{%4,%5,%6,%7},{%8,%9},{%0,%1,%2,%3};"
  :"+f"(d[0]),"+f"(d[1]),"+f"(d[2]),"+f"(d[3]):"r"(a[0]),"r"(a[1]),"r"(a[2]),"r"(a[3]),"r"(b0),"r"(b1));}
__device__ __forceinline__ void CPA(u32 dst,const void* src){
  asm volatile("cp.async.cg.shared.global [%0],[%1],16;"::"r"(dst),"l"(src));}
__device__ __forceinline__ void CPWAIT(){
  asm volatile("cp.async.commit_group;\ncp.async.wait_group 0;":::"memory");}
__device__ __forceinline__ u32 pkh(float a,float b){
  __half2 h=__floats2half2_rn(a,b);return *(u32*)&h;}
__device__ __forceinline__ void split2(float a,float b,u32&h,u32&l){
  float ah=__half2float(__float2half_rn(a)),bh=__half2float(__float2half_rn(b));
  h=pkh(a,b);l=pkh(a-ah,b-bh);}

__device__ __align__(16) __half W0[24576],W1[131072],WF[32768],WP[131072],WB[32768],Q0[16384],Q1[32768];
__device__ float g_a[NS_MAX],g_lg[NS_MAX],g_rgb[NS_MAX*3],g_nrm[NS_MAX*3];
__device__ int g_st[NR_MAX+1];

__device__ __forceinline__ void wsp2h(__half* A,int st,int i,float v){
  __half h=__float2half_rn(v);A[i]=h;A[st+i]=__float2half_rn(v-__half2float(h));}

__global__ void prep(const float* Wg0,const float* Wg1,const float* Wg2,const float* Wc0,const float* Wc1){
  int i=blockIdx.x*256+threadIdx.x;int n=i>>8,k=i&255;
  wsp2h(W1,65536,i,Wg1[k*256+n]);
  wsp2h(WP,65536,i,Wg1[n*256+k]*Wg2[k*16]);
  if(i<12288){int nn=i/48,kk=i%48;wsp2h(W0,12288,i,(kk<39)?Wg0[kk*256+nn]:0.f);}
  if(i<16384){wsp2h(WF,16384,i,(n<16)?Wg2[k*16+n]:0.f);
    wsp2h(WB,16384,i,(n<39)?Wg0[n*256+k]:0.f);
    wsp2h(Q1,16384,i,(n<3)?Wc1[k*3+n]:0.f);}
  if(i<8192){int nn=i/32,kk=i%32;wsp2h(Q0,8192,i,(kk<25)?Wc0[kk*256+nn]:0.f);}
}

// SCH 0: A 2-limb x B 2-limb, 3 products ; 2: A exact x B 2-limb, 2 products
// EPI 0: relu+bias -> 2-limb A + mask ; 1: relu+bias -> 2-limb A ; 2: apply MKA -> 2-limb A ; 3: dump fp32 D
template<int NCH,int KS,int SCH,int EPI>
__device__ void gemm(char* smc,const __half* G,int LST,const float* bias,u32* MK,const u32* MKA){
  u32 sb=sm32(smc);const int tid=threadIdx.x,w=tid>>5,l=tid&31;
  const int mr0=(w&7)*16,lw=w>>3,nc0=lw*32,KB=KS*32;
  u32 ao=(mr0+(l&7)+((l&8)?8:0))*528+((l&16)?16:0);
  u32 bo=(nc0+(l&7)+((l&8)?8:0))*528+((l&16)?16:0);
  float acc[NCH][4][4];
#pragma unroll
  for(int c=0;c<NCH;c++)
#pragma unroll
    for(int j=0;j<4;j++)
#pragma unroll
      for(int q=0;q<4;q++)acc[c][j][q]=0.f;
  for(int ch=0;ch<NCH;ch++){
    __syncthreads();
    for(int i=tid*16;i<64*KB;i+=8192){int r=i/KB,k=i-r*KB;
      CPA(sb+OFF_B+r*528+k,(const char*)G+(size_t)ch*64*KB+i);
      CPA(sb+OFF_B+RB+r*528+k,(const char*)(G+LST)+(size_t)ch*64*KB+i);}
    CPWAIT();
    __syncthreads();
#pragma unroll 2
    for(int ks=0;ks<KS;ks++){
      u32 B0[8],B1[8],A0[4],A1[4];
      LD4(B0,sb+OFF_B+bo+ks*32);LD4(B0+4,sb+OFF_B+bo+16*528+ks*32);
      LD4(B1,sb+OFF_B+RB+bo+ks*32);LD4(B1+4,sb+OFF_B+RB+bo+16*528+ks*32);
      LD4(A0,sb+OFF_A+ao+ks*32);
      if(SCH==0)LD4(A1,sb+OFF_A1+ao+ks*32);
#pragma unroll
      for(int j=0;j<4;j++){
        u32 b0=B0[(j>>1)*4+(j&1)],b1=B0[(j>>1)*4+(j&1)+2];
        MMA(acc[ch][j],A0,b0,b1);
        MMA(acc[ch][j],A0,B1[(j>>1)*4+(j&1)],B1[(j>>1)*4+(j&1)+2]);
        if(SCH==0)MMA(acc[ch][j],A1,b0,b1);
      }
    }
  }
  __syncthreads();
  if(EPI==3){
    float* D=(float*)(smc+OFF_B);int m=mr0+(l>>2);
#pragma unroll
    for(int j=0;j<4;j++){int nn=nc0+8*j+2*(l&3);
      D[m*66+nn]=acc[0][j][0];D[m*66+nn+1]=acc[0][j][1];
      D[(m+8)*66+nn]=acc[0][j][2];D[(m+8)*66+nn+1]=acc[0][j][3];}
  }else{
#pragma unroll
    for(int ch=0;ch<NCH;ch++){
      int m=mr0+(l>>2),wd=ch*2+lw;u32 p0=0,p1=0;
#pragma unroll
      for(int j=0;j<4;j++){
        int nn=ch*64+nc0+8*j+2*(l&3),ps=8*j+2*(l&3);
        float v0=acc[ch][j][0],v1=acc[ch][j][1],v2=acc[ch][j][2],v3=acc[ch][j][3];
        if(EPI<=1){float b0=bias[nn],b1=bias[nn+1];
          v0=fmaxf(v0+b0,0.f);v1=fmaxf(v1+b1,0.f);v2=fmaxf(v2+b0,0.f);v3=fmaxf(v3+b1,0.f);}
        if(EPI==0){if(v0>0.f)p0|=1u<<ps;if(v1>0.f)p0|=1u<<(ps+1);if(v2>0.f)p1|=1u<<ps;if(v3>0.f)p1|=1u<<(ps+1);}
        if(EPI==2){u32 k0=MKA[m*8+wd],k1=MKA[(m+8)*8+wd];
          if(!((k0>>ps)&1))v0=0.f;if(!((k0>>(ps+1))&1))v1=0.f;
          if(!((k1>>ps)&1))v2=0.f;if(!((k1>>(ps+1))&1))v3=0.f;}
        u32 h,lo;
        split2(v0,v1,h,lo);
        *(u32*)(smc+OFF_A+m*528+nn*2)=h;*(u32*)(smc+OFF_A1+m*528+nn*2)=lo;
        split2(v2,v3,h,lo);
        *(u32*)(smc+OFF_A+(m+8)*528+nn*2)=h;*(u32*)(smc+OFF_A1+(m+8)*528+nn*2)=lo;}
      if(EPI==0){
        p0|=__shfl_xor_sync(~0u,p0,1);p0|=__shfl_xor_sync(~0u,p0,2);
        p1|=__shfl_xor_sync(~0u,p1,1);p1|=__shfl_xor_sync(~0u,p1,2);
        if((l&3)==0){MK[m*8+wd]=p0;MK[(m+8)*8+wd]=p1;}}}
  }
  __syncthreads();
}

template<bool RAND>
__global__ void __launch_bounds__(512,1) fused(
  const float* __restrict__ rays_o,const float* __restrict__ rays_d,
  const int* __restrict__ ridx,const float* __restrict__ t_starts,
  const float* __restrict__ pts,const float* __restrict__ s_var,
  const float* __restrict__ bg0,const float* __restrict__ bg1,
  const float* __restrict__ bg2,const float* __restrict__ bc0,
  const float* __restrict__ bc1,
  float* __restrict__ out,int nn,long long off_sdf){
  extern __shared__ char smc[];
  float* PD=(float*)(smc+OFF_PD);float* FS=(float*)(smc+OFF_FS);
  u32* MK0=(u32*)(smc+OFF_MK0);u32* MK1=(u32*)(smc+OFF_MK1);
  const int tid=threadIdx.x;const int gs=blockIdx.x*128+tid;
  if(tid<128){
    int si=(gs<nn)?gs:nn-1;float px,py,pz;
    if(RAND){px=pts[si*3];py=pts[si*3+1];pz=pts[si*3+2];}
    else{
      int ray=ridx[si];
      float ox=rays_o[ray*3],oy=rays_o[ray*3+1],oz=rays_o[ray*3+2];
      float dx=rays_d[ray*3],dy=rays_d[ray*3+1],dz=rays_d[ray*3+2];
      float inv=1.f/(sqrtf(dx*dx+dy*dy+dz*dz)+1e-10f);
      dx*=inv;dy*=inv;dz*=inv;
      float mid=t_starts[si]+0.0025f;
      px=fmaf(dx,mid,ox);py=fmaf(dy,mid,oy);pz=fmaf(dz,mid,oz);
      PD[tid*8]=px;PD[tid*8+1]=py;PD[tid*8+2]=pz;
      PD[tid*8+3]=dx;PD[tid*8+4]=dy;PD[tid*8+5]=dz;}
    float pe[48];
#pragma unroll
    for(int j=39;j<48;j++)pe[j]=0.f;
    pe[0]=px;pe[1]=py;pe[2]=pz;
    float f=PI_F;
#pragma unroll
    for(int i=0;i<6;i++){
      float sx,cx,sy,cy,sz,cz;
      sincosf(f*px,&sx,&cx);sincosf(f*py,&sy,&cy);sincosf(f*pz,&sz,&cz);
      pe[3+6*i]=sx;pe[4+6*i]=sy;pe[5+6*i]=sz;pe[6+6*i]=cx;pe[7+6*i]=cy;pe[8+6*i]=cz;f*=2.f;}
#pragma unroll
    for(int j=0;j<24;j++){u32 h,lo;split2(pe[2*j],pe[2*j+1],h,lo);
      *(u32*)(smc+OFF_A+tid*528+j*4)=h;*(u32*)(smc+OFF_A1+tid*528+j*4)=lo;}
  }
  gemm<4,3,0,0>(smc,W0,12288,bg0,MK0,0);
  gemm<4,16,0,0>(smc,W1,65536,bg1,MK1,0);
  gemm<1,16,0,3>(smc,WF,16384,0,0,0);
  {float* D=(float*)(smc+OFF_B);
   if(tid<128){
     float sdf=D[tid*66]+bg2[0];FS[tid*16]=sdf;
     if(gs<nn)out[off_sdf+gs]=sdf;
     for(int c=1;c<16;c++)FS[tid*16+c]=D[tid*66+c]+bg2[c];}}
  if(RAND)return;
  for(int idx=tid;idx<128*128;idx+=512){int r=idx>>7,j=idx&127;
    u32 mk=MK1[r*8+(j>>4)];int ps=(j&15)*2;
    *(u32*)(smc+OFF_A+r*528+j*4)=(((mk>>ps)&1)?0x3C00u:0u)|(((mk>>(ps+1))&1)?0x3C000000u:0u);}
  gemm<4,16,2,2>(smc,WP,65536,0,0,MK0);
  gemm<1,16,0,3>(smc,WB,16384,0,0,0);
  if(tid<128){
    float* D=(float*)(smc+OFF_B);
    float px=PD[tid*8],py=PD[tid*8+1],pz=PD[tid*8+2];
    float dx=PD[tid*8+3],dy=PD[tid*8+4],dz=PD[tid*8+5];
    float g0=D[tid*66],g1=D[tid*66+1],g2=D[tid*66+2];
    float f=PI_F;
#pragma unroll
    for(int i=0;i<6;i++){
      float sx,cx,sy,cy,sz,cz;
      sincosf(f*px,&sx,&cx);sincosf(f*py,&sy,&cy);sincosf(f*pz,&sz,&cz);
      g0+=f*(cx*D[tid*66+3+6*i]-sx*D[tid*66+6+6*i]);
      g1+=f*(cy*D[tid*66+4+6*i]-sy*D[tid*66+7+6*i]);
      g2+=f*(cz*D[tid*66+5+6*i]-sz*D[tid*66+8+6*i]);f*=2.f;}
    float len=sqrtf(g0*g0+g1*g1+g2*g2),ninv=1.f/(len+1e-10f);
    float nx=g0*ninv,ny=g1*ninv,nz=g2*ninv;
    float inv_s=fminf(fmaxf(expf(s_var[0]),1e-6f),1e6f);
    float dsdf=fminf(g0*dx+g1*dy+g2*dz,0.f);
    float sdf=FS[tid*16];
    float cdf=1.f/(1.f+expf(-inv_s*sdf));
    float rho=fmaxf(inv_s*(cdf-1.f)*dsdf,0.f);
    float a=fminf(fmaxf(1.f-expf(-rho*0.005f),0.f),1.f-1e-7f);
    if(gs<nn){g_a[gs]=a;g_lg[gs]=log1pf(-a);
      g_nrm[gs*3]=nx;g_nrm[gs*3+1]=ny;g_nrm[gs*3+2]=nz;}
    float ci[32];
#pragma unroll
    for(int j=25;j<32;j++)ci[j]=0.f;
    ci[0]=dx;ci[1]=dy;ci[2]=dz;
#pragma unroll
    for(int c=0;c<16;c++)ci[3+c]=FS[tid*16+c];
    ci[19]=px;ci[20]=py;ci[21]=pz;ci[22]=nx;ci[23]=ny;ci[24]=nz;
#pragma unroll
    for(int j=0;j<16;j++){u32 h,lo;split2(ci[2*j],ci[2*j+1],h,lo);
      *(u32*)(smc+OFF_A+tid*528+j*4)=h;*(u32*)(smc+OFF_A1+tid*528+j*4)=lo;}
  }
  gemm<4,2,0,1>(smc,Q0,8192,bc0,0,0);
  gemm<1,16,0,3>(smc,Q1,16384,0,0,0);
  if(tid<128&&gs<nn){
    float* D=(float*)(smc+OFF_B);
    for(int c=0;c<3;c++)g_rgb[gs*3+c]=1.f/(1.f+expf(-(D[tid*66+c]+bc1[c])));}
}

__global__ void ray_starts(const int* __restrict__ ridx,int n_rays,int n_samples){
  int r=blockIdx.x*256+threadIdx.x;
  if(r>n_rays)return;
  int lo=0,hi=n_samples;
  while(lo<hi){int m=(lo+hi)>>1;if(ridx[m]<r)lo=m+1;else hi=m;}
  g_st[r]=lo;
}

__global__ void composite(const float* __restrict__ t_starts,float* __restrict__ out,
                          int n_rays,long long off_c,long long off_n,
                          long long off_o,long long off_d,long long off_w){
  int ray=(blockIdx.x*blockDim.x+threadIdx.x)>>5;
  int lane=threadIdx.x&31;
  if(ray>=n_rays)return;
  int s0=g_st[ray],s1=g_st[ray+1];
  float carry=0.f,op=0.f,dep=0.f,c0=0.f,c1=0.f,c2=0.f,n0=0.f,n1=0.f,n2=0.f;
  for(int base=s0;base<s1;base+=32){
    int s=base+lane;bool v=s<s1;
    float lg=v?g_lg[s]:0.f,incl=lg;
#pragma unroll
    for(int o=1;o<32;o<<=1){float t=__shfl_up_sync(~0u,incl,o);if(lane>=o)incl+=t;}
    if(v){
      float wgt=g_a[s]*expf(carry+incl-lg);
      out[off_w+s]=wgt;
      float mid=t_starts[s]+0.0025f;
      op+=wgt;dep+=wgt*mid;
      c0+=wgt*g_rgb[s*3];c1+=wgt*g_rgb[s*3+1];c2+=wgt*g_rgb[s*3+2];
      n0+=wgt*g_nrm[s*3];n1+=wgt*g_nrm[s*3+1];n2+=wgt*g_nrm[s*3+2];}
    carry+=__shfl_sync(~0u,incl,31);
  }
#pragma unroll
  for(int o=16;o;o>>=1){
    op+=__shfl_xor_sync(~0u,op,o);dep+=__shfl_xor_sync(~0u,dep,o);
    c0+=__shfl_xor_sync(~0u,c0,o);c1+=__shfl_xor_sync(~0u,c1,o);
    c2+=__shfl_xor_sync(~0u,c2,o);n0+=__shfl_xor_sync(~0u,n0,o);
    n1+=__shfl_xor_sync(~0u,n1,o);n2+=__shfl_xor_sync(~0u,n2,o);}
  if(lane==0){
    out[off_o+ray]=op;out[off_d+ray]=dep;
    out[off_c+ray*3]=c0;out[off_c+ray*3+1]=c1;out[off_c+ray*3+2]=c2;
    float nl=sqrtf(n0*n0+n1*n1+n2*n2),ninv=1.f/(nl+1e-10f);
    out[off_n+ray*3]=n0*ninv;out[off_n+ray*3+1]=n1*ninv;out[off_n+ray*3+2]=n2*ninv;}
}

extern "C" void kernel_launch(void* const* d_in,const int* in_sizes,int n_in,
                              void* d_out,int out_size){
  const float* rays_o=(const float*)d_in[0];
  const float* rays_d=(const float*)d_in[1];
  const int*   ridx  =(const int*)d_in[2];
  const float* t_st  =(const float*)d_in[3];
  const float* rpts  =(const float*)d_in[4];
  const float* s_var =(const float*)d_in[5];
  const float* Wg0=(const float*)d_in[6];  const float* bg0=(const float*)d_in[7];
  const float* Wg1=(const float*)d_in[8];  const float* bg1=(const float*)d_in[9];
  const float* Wg2=(const float*)d_in[10]; const float* bg2=(const float*)d_in[11];
  const float* Wc0=(const float*)d_in[12]; const float* bc0=(const float*)d_in[13];
  const float* Wc1=(const float*)d_in[14]; const float* bc1=(const float*)d_in[15];
  float* out=(float*)d_out;
  int n_rays=in_sizes[0]/3,n_samples=in_sizes[2],n_rand=in_sizes[4]/3;
  long long off_c=0;
  long long off_n=off_c+3LL*n_rays;
  long long off_o=off_n+3LL*n_rays;
  long long off_d=off_o+n_rays;
  long long off_w=off_d+n_rays;
  long long off_s=off_w+n_samples;
  long long off_r=off_s+n_samples;
  cudaFuncSetAttribute(fused<false>,cudaFuncAttributeMaxDynamicSharedMemorySize,SMEM_BYTES);
  cudaFuncSetAttribute(fused<true>, cudaFuncAttributeMaxDynamicSharedMemorySize,SMEM_BYTES);
  prep<<<256,256>>>(Wg0,Wg1,Wg2,Wc0,Wc1);
  fused<false><<<(n_samples+127)/128,512,SMEM_BYTES>>>(
    rays_o,rays_d,ridx,t_st,rpts,s_var,bg0,bg1,bg2,bc0,bc1,out,n_samples,off_s);
  fused<true><<<(n_rand+127)/128,512,SMEM_BYTES>>>(
    rays_o,rays_d,ridx,t_st,rpts,s_var,bg0,bg1,bg2,bc0,bc1,out,n_rand,off_r);
  ray_starts<<<(n_rays+256)/256,256>>>(ridx,n_rays,n_samples);
  composite<<<(n_rays*32+255)/256,256>>>(t_st,out,n_rays,off_c,off_n,off_o,off_d,off_w);
}